// round 1
// baseline (speedup 1.0000x reference)
#include <cuda_runtime.h>
#include <cstddef>

// ---------------------------------------------------------------------------
// ContextNet (RIFE-style) on GB300.
// Levels: (Cin,Cout,Hin): (3,16,512) (16,32,256) (32,64,128) (64,128,64)
// Per level: conv3x3 s2 + PReLU -> conv3x3 s1 + PReLU -> halve flow -> splat avg
// ---------------------------------------------------------------------------

#define NB 16  // batch

// Scratch (static device globals; allocation-free per harness rules)
__device__ float g_fa[(size_t)16 * 16 * 256 * 256];   // conv_a output (max 16.7M floats)
__device__ float g_fb[(size_t)16 * 16 * 256 * 256];   // conv_b output / next level input
__device__ float g_flA[(size_t)16 * 2 * 256 * 256];   // halved flow ping
__device__ float g_flB[(size_t)16 * 2 * 256 * 256];   // halved flow pong
__device__ float g_cnt[(size_t)16 * 256 * 256];       // splat count channel

// ---------------------------------------------------------------------------
// Direct 3x3 conv + bias + PReLU.
// Block: (32,8) threads; each thread computes 4 outputs along y for one
// (n, co). Weights for this co staged in shared memory.
// Grid: (Wout/32, Hout/32, NB*Cout). All spatial dims are multiples of 32.
// ---------------------------------------------------------------------------
template <int STRIDE>
__global__ void conv3x3_prelu_kernel(const float* __restrict__ in,
                                     const float* __restrict__ wt,
                                     const float* __restrict__ bias,
                                     const float* __restrict__ alpha,
                                     float* __restrict__ out,
                                     int Cin, int Cout, int Hin, int Win) {
    const int Hout = Hin / STRIDE;
    const int Wout = Win / STRIDE;
    const int co = blockIdx.z % Cout;
    const int n  = blockIdx.z / Cout;

    extern __shared__ float sw[];
    const int tid = threadIdx.y * 32 + threadIdx.x;
    const int nw = Cin * 9;
    for (int i = tid; i < nw; i += 256) sw[i] = wt[co * nw + i];
    __syncthreads();

    const int x  = blockIdx.x * 32 + threadIdx.x;
    const int y0 = blockIdx.y * 32 + threadIdx.y * 4;

    float acc[4] = {0.f, 0.f, 0.f, 0.f};
    const float* ib = in + (size_t)n * Cin * Hin * Win;

    for (int ci = 0; ci < Cin; ci++) {
        const float* ip = ib + (size_t)ci * Hin * Win;
        const float* w9 = sw + ci * 9;
        if (STRIDE == 1) {
            float v[6][3];
#pragma unroll
            for (int r = 0; r < 6; r++) {
                int iy = y0 - 1 + r;
                bool yok = ((unsigned)iy < (unsigned)Hin);
#pragma unroll
                for (int c = 0; c < 3; c++) {
                    int ix = x - 1 + c;
                    v[r][c] = (yok && (unsigned)ix < (unsigned)Win)
                                  ? ip[iy * Win + ix] : 0.f;
                }
            }
#pragma unroll
            for (int j = 0; j < 4; j++)
#pragma unroll
                for (int ky = 0; ky < 3; ky++)
#pragma unroll
                    for (int kx = 0; kx < 3; kx++)
                        acc[j] = fmaf(v[j + ky][kx], w9[ky * 3 + kx], acc[j]);
        } else {  // STRIDE == 2
            float v[9][3];
#pragma unroll
            for (int r = 0; r < 9; r++) {
                int iy = 2 * y0 - 1 + r;
                bool yok = ((unsigned)iy < (unsigned)Hin);
#pragma unroll
                for (int c = 0; c < 3; c++) {
                    int ix = 2 * x - 1 + c;
                    v[r][c] = (yok && (unsigned)ix < (unsigned)Win)
                                  ? ip[iy * Win + ix] : 0.f;
                }
            }
#pragma unroll
            for (int j = 0; j < 4; j++)
#pragma unroll
                for (int ky = 0; ky < 3; ky++)
#pragma unroll
                    for (int kx = 0; kx < 3; kx++)
                        acc[j] = fmaf(v[2 * j + ky][kx], w9[ky * 3 + kx], acc[j]);
        }
    }

    const float bv = bias[co];
    const float av = alpha[co];
    if (x < Wout) {
        float* ob = out + ((size_t)(n * Cout + co) * Hout) * Wout;
#pragma unroll
        for (int j = 0; j < 4; j++) {
            int y = y0 + j;
            if (y < Hout) {
                float o = acc[j] + bv;
                o = (o >= 0.f) ? o : av * o;
                ob[y * Wout + x] = o;
            }
        }
    }
}

// ---------------------------------------------------------------------------
// Flow halving: 2x2 mean * 0.5 == sum * 0.125. in: [NB*2, 2H, 2W] -> out [NB*2,H,W]
// ---------------------------------------------------------------------------
__global__ void halve_flow_kernel(const float* __restrict__ in,
                                  float* __restrict__ out, int Hout, int Wout) {
    int idx = blockIdx.x * blockDim.x + threadIdx.x;
    int total = NB * 2 * Hout * Wout;
    if (idx >= total) return;
    int w = idx % Wout;
    int h = (idx / Wout) % Hout;
    int nc = idx / (Wout * Hout);
    int Win = 2 * Wout;
    const float* ip = in + (size_t)nc * (4 * Hout * Wout);
    const float* r0 = ip + (2 * h) * Win + 2 * w;
    const float* r1 = r0 + Win;
    out[idx] = (r0[0] + r0[1] + r1[0] + r1[1]) * 0.125f;
}

// ---------------------------------------------------------------------------
// Forward bilinear splat (scatter-add of features and a ones/count channel).
// One thread per source pixel (n,y,x).
// ---------------------------------------------------------------------------
__global__ void splat_add_kernel(const float* __restrict__ feat,
                                 const float* __restrict__ flow,
                                 float* __restrict__ num,
                                 float* __restrict__ cnt,
                                 int C, int H, int W) {
    int idx = blockIdx.x * blockDim.x + threadIdx.x;
    int HW = H * W;
    int total = NB * HW;
    if (idx >= total) return;
    int n = idx / HW;
    int p = idx % HW;
    int y = p / W;
    int x = p % W;

    const float* fb = flow + (size_t)n * 2 * HW;
    float fx = fb[p] + (float)x;
    float fy = fb[HW + p] + (float)y;

    float x0f = floorf(fx), y0f = floorf(fy);
    int ix0 = (int)x0f, iy0 = (int)y0f;
    float wx1 = fx - x0f, wy1 = fy - y0f;
    float wx0 = 1.f - wx1, wy0 = 1.f - wy1;

    int   xi[4] = {ix0, ix0 + 1, ix0,     ix0 + 1};
    int   yi[4] = {iy0, iy0,     iy0 + 1, iy0 + 1};
    float wv[4] = {wx0 * wy0, wx1 * wy0, wx0 * wy1, wx1 * wy1};
    int   tgt[4];
    bool  ok[4];
#pragma unroll
    for (int k = 0; k < 4; k++) {
        ok[k] = ((unsigned)xi[k] < (unsigned)W) && ((unsigned)yi[k] < (unsigned)H);
        tgt[k] = yi[k] * W + xi[k];
        if (ok[k]) atomicAdd(&cnt[n * HW + tgt[k]], wv[k]);
    }

    const float* src = feat + (size_t)n * C * HW + p;
    float* dst = num + (size_t)n * C * HW;
    for (int c = 0; c < C; c++) {
        float s = src[(size_t)c * HW];
        float* dc = dst + (size_t)c * HW;
#pragma unroll
        for (int k = 0; k < 4; k++)
            if (ok[k]) atomicAdd(&dc[tgt[k]], s * wv[k]);
    }
}

// ---------------------------------------------------------------------------
// num /= (cnt == 0 ? 1 : cnt)
// ---------------------------------------------------------------------------
__global__ void norm_div_kernel(float* __restrict__ num,
                                const float* __restrict__ cnt,
                                int C, int HW) {
    int idx = blockIdx.x * blockDim.x + threadIdx.x;
    int total = NB * C * HW;
    if (idx >= total) return;
    int n = idx / (C * HW);
    int p = idx % HW;
    float cv = cnt[n * HW + p];
    num[idx] = num[idx] / ((cv == 0.f) ? 1.f : cv);
}

// ---------------------------------------------------------------------------
// Host launcher
// ---------------------------------------------------------------------------
extern "C" void kernel_launch(void* const* d_in, const int* in_sizes, int n_in,
                              void* d_out, int out_size) {
    const float* img  = (const float*)d_in[0];
    const float* flow = (const float*)d_in[1];
    float* out = (float*)d_out;

    float *fa, *fb, *flA, *flB, *cnt;
    cudaGetSymbolAddress((void**)&fa,  g_fa);
    cudaGetSymbolAddress((void**)&fb,  g_fb);
    cudaGetSymbolAddress((void**)&flA, g_flA);
    cudaGetSymbolAddress((void**)&flB, g_flB);
    cudaGetSymbolAddress((void**)&cnt, g_cnt);
    float* flow_bufs[2] = {flA, flB};

    // zero the whole output (splat accumulates into it)
    cudaMemsetAsync(d_out, 0, (size_t)out_size * sizeof(float));

    const int Cin[4]  = {3, 16, 32, 64};
    const int Cout[4] = {16, 32, 64, 128};
    const int Hin[4]  = {512, 256, 128, 64};

    size_t off = 0;
    const float* feat_in = img;
    const float* flow_in = flow;

    for (int L = 0; L < 4; L++) {
        const int ci = Cin[L], co = Cout[L], hi = Hin[L], ho = hi / 2;
        const float* wA = (const float*)d_in[2 + 6 * L + 0];
        const float* bA = (const float*)d_in[2 + 6 * L + 1];
        const float* aA = (const float*)d_in[2 + 6 * L + 2];
        const float* wB = (const float*)d_in[2 + 6 * L + 3];
        const float* bB = (const float*)d_in[2 + 6 * L + 4];
        const float* aB = (const float*)d_in[2 + 6 * L + 5];

        dim3 blk(32, 8);
        dim3 grd(ho / 32, ho / 32, NB * co);

        // conv_a: stride 2, Hin -> ho
        conv3x3_prelu_kernel<2><<<grd, blk, ci * 9 * sizeof(float)>>>(
            feat_in, wA, bA, aA, fa, ci, co, hi, hi);
        // conv_b: stride 1 at ho
        conv3x3_prelu_kernel<1><<<grd, blk, co * 9 * sizeof(float)>>>(
            fa, wB, bB, aB, fb, co, co, ho, ho);

        // halve flow: hi -> ho
        float* fl = flow_bufs[L & 1];
        {
            int nfl = NB * 2 * ho * ho;
            halve_flow_kernel<<<(nfl + 255) / 256, 256>>>(flow_in, fl, ho, ho);
        }

        // splat into output region
        cudaMemsetAsync(cnt, 0, (size_t)NB * ho * ho * sizeof(float));
        float* numL = out + off;
        {
            int np = NB * ho * ho;
            splat_add_kernel<<<(np + 255) / 256, 256>>>(fb, fl, numL, cnt, co, ho, ho);
        }
        {
            int ne = NB * co * ho * ho;
            norm_div_kernel<<<(ne + 255) / 256, 256>>>(numL, cnt, co, ho * ho);
        }

        off += (size_t)NB * co * ho * ho;
        feat_in = fb;
        flow_in = fl;
    }
}

// round 2
// speedup vs baseline: 1.6006x; 1.6006x over previous
#include <cuda_runtime.h>
#include <cstddef>

// ---------------------------------------------------------------------------
// ContextNet (RIFE-style) on GB300.
// Levels: (Cin,Cout,Hin): (3,16,512) (16,32,256) (32,64,128) (64,128,64)
// Per level: conv3x3 s2 + PReLU -> conv3x3 s1 + PReLU -> halve flow -> splat avg
// ---------------------------------------------------------------------------

#define NB 16  // batch

// Scratch (static device globals; allocation-free per harness rules)
__device__ float g_fa[(size_t)16 * 16 * 256 * 256];   // conv_a output
__device__ float g_fb[(size_t)16 * 16 * 256 * 256];   // conv_b output / next level input
__device__ float g_flA[(size_t)16 * 2 * 256 * 256];   // halved flow ping
__device__ float g_flB[(size_t)16 * 2 * 256 * 256];   // halved flow pong
__device__ float g_cnt[(size_t)16 * 256 * 256];       // splat count channel

// ---------------------------------------------------------------------------
// Direct 3x3 conv + bias + PReLU, register-blocked: each thread computes
// 4 output channels x 4 output rows (16 accumulators).
// Block (32,8). Grid: (Wout/32, Hout/32, NB * Cout/4).
// Weights for the block's 4 co staged contiguously in shared memory.
// ---------------------------------------------------------------------------
template <int STRIDE>
__global__ void conv3x3_prelu_c4(const float* __restrict__ in,
                                 const float* __restrict__ wt,
                                 const float* __restrict__ bias,
                                 const float* __restrict__ alpha,
                                 float* __restrict__ out,
                                 int Cin, int Cout, int Hin, int Win) {
    const int Hout = Hin / STRIDE;
    const int Wout = Win / STRIDE;
    const int cg = Cout >> 2;
    const int co0 = (blockIdx.z % cg) * 4;
    const int n   = blockIdx.z / cg;

    extern __shared__ float sw[];        // [4][Cin][9], same layout as global
    const int tid = threadIdx.y * 32 + threadIdx.x;
    const int nw = 4 * Cin * 9;
    const float* wsrc = wt + (size_t)co0 * Cin * 9;
    for (int i = tid; i < nw; i += 256) sw[i] = wsrc[i];
    __syncthreads();

    const int x  = blockIdx.x * 32 + threadIdx.x;
    const int y0 = blockIdx.y * 32 + threadIdx.y * 4;

    float acc[4][4];
#pragma unroll
    for (int c = 0; c < 4; c++)
#pragma unroll
        for (int j = 0; j < 4; j++) acc[c][j] = 0.f;

    const float* ib = in + (size_t)n * Cin * Hin * Win;

    for (int ci = 0; ci < Cin; ci++) {
        const float* ip = ib + (size_t)ci * Hin * Win;
        if (STRIDE == 1) {
            float v[6][3];
#pragma unroll
            for (int r = 0; r < 6; r++) {
                int iy = y0 - 1 + r;
                bool yok = ((unsigned)iy < (unsigned)Hin);
#pragma unroll
                for (int c = 0; c < 3; c++) {
                    int ix = x - 1 + c;
                    v[r][c] = (yok && (unsigned)ix < (unsigned)Win)
                                  ? ip[iy * Win + ix] : 0.f;
                }
            }
#pragma unroll
            for (int c4 = 0; c4 < 4; c4++) {
                const float* w9 = sw + (c4 * Cin + ci) * 9;
                float w[9];
#pragma unroll
                for (int k = 0; k < 9; k++) w[k] = w9[k];
#pragma unroll
                for (int j = 0; j < 4; j++)
#pragma unroll
                    for (int ky = 0; ky < 3; ky++)
#pragma unroll
                        for (int kx = 0; kx < 3; kx++)
                            acc[c4][j] = fmaf(v[j + ky][kx], w[ky * 3 + kx], acc[c4][j]);
            }
        } else {  // STRIDE == 2
            float v[9][3];
#pragma unroll
            for (int r = 0; r < 9; r++) {
                int iy = 2 * y0 - 1 + r;
                bool yok = ((unsigned)iy < (unsigned)Hin);
#pragma unroll
                for (int c = 0; c < 3; c++) {
                    int ix = 2 * x - 1 + c;
                    v[r][c] = (yok && (unsigned)ix < (unsigned)Win)
                                  ? ip[iy * Win + ix] : 0.f;
                }
            }
#pragma unroll
            for (int c4 = 0; c4 < 4; c4++) {
                const float* w9 = sw + (c4 * Cin + ci) * 9;
                float w[9];
#pragma unroll
                for (int k = 0; k < 9; k++) w[k] = w9[k];
#pragma unroll
                for (int j = 0; j < 4; j++)
#pragma unroll
                    for (int ky = 0; ky < 3; ky++)
#pragma unroll
                        for (int kx = 0; kx < 3; kx++)
                            acc[c4][j] = fmaf(v[2 * j + ky][kx], w[ky * 3 + kx], acc[c4][j]);
            }
        }
    }

#pragma unroll
    for (int c4 = 0; c4 < 4; c4++) {
        const int co = co0 + c4;
        const float bv = bias[co];
        const float av = alpha[co];
        float* ob = out + ((size_t)(n * Cout + co) * Hout) * Wout;
#pragma unroll
        for (int j = 0; j < 4; j++) {
            float o = acc[c4][j] + bv;
            o = (o >= 0.f) ? o : av * o;
            ob[(y0 + j) * Wout + x] = o;
        }
    }
}

// ---------------------------------------------------------------------------
// Flow halving: 2x2 mean * 0.5 == sum * 0.125
// ---------------------------------------------------------------------------
__global__ void halve_flow_kernel(const float* __restrict__ in,
                                  float* __restrict__ out, int Hout, int Wout) {
    int idx = blockIdx.x * blockDim.x + threadIdx.x;
    int total = NB * 2 * Hout * Wout;
    if (idx >= total) return;
    int w = idx % Wout;
    int h = (idx / Wout) % Hout;
    int nc = idx / (Wout * Hout);
    int Win = 2 * Wout;
    const float* ip = in + (size_t)nc * (4 * Hout * Wout);
    const float* r0 = ip + (2 * h) * Win + 2 * w;
    const float* r1 = r0 + Win;
    out[idx] = (r0[0] + r0[1] + r1[0] + r1[1]) * 0.125f;
}

// ---------------------------------------------------------------------------
// Forward bilinear splat (scatter-add of features and a count channel).
// ---------------------------------------------------------------------------
__global__ void splat_add_kernel(const float* __restrict__ feat,
                                 const float* __restrict__ flow,
                                 float* __restrict__ num,
                                 float* __restrict__ cnt,
                                 int C, int H, int W) {
    int idx = blockIdx.x * blockDim.x + threadIdx.x;
    int HW = H * W;
    int total = NB * HW;
    if (idx >= total) return;
    int n = idx / HW;
    int p = idx % HW;
    int y = p / W;
    int x = p % W;

    const float* fb = flow + (size_t)n * 2 * HW;
    float fx = fb[p] + (float)x;
    float fy = fb[HW + p] + (float)y;

    float x0f = floorf(fx), y0f = floorf(fy);
    int ix0 = (int)x0f, iy0 = (int)y0f;
    float wx1 = fx - x0f, wy1 = fy - y0f;
    float wx0 = 1.f - wx1, wy0 = 1.f - wy1;

    int   xi[4] = {ix0, ix0 + 1, ix0,     ix0 + 1};
    int   yi[4] = {iy0, iy0,     iy0 + 1, iy0 + 1};
    float wv[4] = {wx0 * wy0, wx1 * wy0, wx0 * wy1, wx1 * wy1};
    int   tgt[4];
    bool  ok[4];
#pragma unroll
    for (int k = 0; k < 4; k++) {
        ok[k] = ((unsigned)xi[k] < (unsigned)W) && ((unsigned)yi[k] < (unsigned)H);
        tgt[k] = yi[k] * W + xi[k];
        if (ok[k]) atomicAdd(&cnt[n * HW + tgt[k]], wv[k]);
    }

    const float* src = feat + (size_t)n * C * HW + p;
    float* dst = num + (size_t)n * C * HW;
    for (int c = 0; c < C; c++) {
        float s = src[(size_t)c * HW];
        float* dc = dst + (size_t)c * HW;
#pragma unroll
        for (int k = 0; k < 4; k++)
            if (ok[k]) atomicAdd(&dc[tgt[k]], s * wv[k]);
    }
}

// ---------------------------------------------------------------------------
// num /= (cnt == 0 ? 1 : cnt)
// ---------------------------------------------------------------------------
__global__ void norm_div_kernel(float* __restrict__ num,
                                const float* __restrict__ cnt,
                                int C, int HW) {
    int idx = blockIdx.x * blockDim.x + threadIdx.x;
    int total = NB * C * HW;
    if (idx >= total) return;
    int n = idx / (C * HW);
    int p = idx % HW;
    float cv = cnt[n * HW + p];
    num[idx] = num[idx] / ((cv == 0.f) ? 1.f : cv);
}

// ---------------------------------------------------------------------------
// Host launcher
// ---------------------------------------------------------------------------
extern "C" void kernel_launch(void* const* d_in, const int* in_sizes, int n_in,
                              void* d_out, int out_size) {
    const float* img  = (const float*)d_in[0];
    const float* flow = (const float*)d_in[1];
    float* out = (float*)d_out;

    float *fa, *fb, *flA, *flB, *cnt;
    cudaGetSymbolAddress((void**)&fa,  g_fa);
    cudaGetSymbolAddress((void**)&fb,  g_fb);
    cudaGetSymbolAddress((void**)&flA, g_flA);
    cudaGetSymbolAddress((void**)&flB, g_flB);
    cudaGetSymbolAddress((void**)&cnt, g_cnt);
    float* flow_bufs[2] = {flA, flB};

    cudaMemsetAsync(d_out, 0, (size_t)out_size * sizeof(float));

    const int Cin[4]  = {3, 16, 32, 64};
    const int Cout[4] = {16, 32, 64, 128};
    const int Hin[4]  = {512, 256, 128, 64};

    size_t off = 0;
    const float* feat_in = img;
    const float* flow_in = flow;

    for (int L = 0; L < 4; L++) {
        const int ci = Cin[L], co = Cout[L], hi = Hin[L], ho = hi / 2;
        const float* wA = (const float*)d_in[2 + 6 * L + 0];
        const float* bA = (const float*)d_in[2 + 6 * L + 1];
        const float* aA = (const float*)d_in[2 + 6 * L + 2];
        const float* wB = (const float*)d_in[2 + 6 * L + 3];
        const float* bB = (const float*)d_in[2 + 6 * L + 4];
        const float* aB = (const float*)d_in[2 + 6 * L + 5];

        dim3 blk(32, 8);
        dim3 grd(ho / 32, ho / 32, NB * (co / 4));

        // conv_a: stride 2, hi -> ho
        conv3x3_prelu_c4<2><<<grd, blk, 4 * ci * 9 * sizeof(float)>>>(
            feat_in, wA, bA, aA, fa, ci, co, hi, hi);
        // conv_b: stride 1 at ho
        conv3x3_prelu_c4<1><<<grd, blk, 4 * co * 9 * sizeof(float)>>>(
            fa, wB, bB, aB, fb, co, co, ho, ho);

        // halve flow: hi -> ho
        float* fl = flow_bufs[L & 1];
        {
            int nfl = NB * 2 * ho * ho;
            halve_flow_kernel<<<(nfl + 255) / 256, 256>>>(flow_in, fl, ho, ho);
        }

        // splat into output region
        cudaMemsetAsync(cnt, 0, (size_t)NB * ho * ho * sizeof(float));
        float* numL = out + off;
        {
            int np = NB * ho * ho;
            splat_add_kernel<<<(np + 255) / 256, 256>>>(fb, fl, numL, cnt, co, ho, ho);
        }
        {
            int ne = NB * co * ho * ho;
            norm_div_kernel<<<(ne + 255) / 256, 256>>>(numL, cnt, co, ho * ho);
        }

        off += (size_t)NB * co * ho * ho;
        feat_in = fb;
        flow_in = fl;
    }
}

// round 3
// speedup vs baseline: 2.0328x; 1.2700x over previous
#include <cuda_runtime.h>
#include <cstddef>

// ---------------------------------------------------------------------------
// ContextNet (RIFE-style) on GB300, padded-buffer edition.
// Levels: (Cin,Cout,Hin): (3,16,512) (16,32,256) (32,64,128) (64,128,64)
// Intermediate feature maps stored with a 1-pixel zero halo so conv loads
// need no bounds predication.
// ---------------------------------------------------------------------------

#define NB 16  // batch

// Padded per-level regions (disjoint):
//  sum over L of NB*co*(ho+2)^2  =  ~32.6M floats per buffer
__device__ float g_fa[33000000];
__device__ float g_fb[33000000];
__device__ float g_flA[(size_t)16 * 2 * 256 * 256];
__device__ float g_flB[(size_t)16 * 2 * 256 * 256];
__device__ float g_cnt[(size_t)16 * 256 * 256];

// ---------------------------------------------------------------------------
// Zero the 1-px border of NC padded planes of logical size HxW (pitch W+2).
// base points at the region start (corner of the halo).
// ---------------------------------------------------------------------------
__global__ void zero_border_kernel(float* __restrict__ base, int NC, int H, int W) {
    int per = 2 * (W + 2) + 2 * H;
    int idx = blockIdx.x * blockDim.x + threadIdx.x;
    if (idx >= NC * per) return;
    int c = idx / per, r = idx % per;
    float* p = base + (size_t)c * (H + 2) * (W + 2);
    if (r < W + 2) {
        p[r] = 0.f;
    } else if (r < 2 * (W + 2)) {
        p[(size_t)(H + 1) * (W + 2) + (r - (W + 2))] = 0.f;
    } else {
        int rr = r - 2 * (W + 2);
        int y = rr % H;
        bool right = rr >= H;
        p[(size_t)(y + 1) * (W + 2) + (right ? (W + 1) : 0)] = 0.f;
    }
}

// ---------------------------------------------------------------------------
// Direct 3x3 conv + bias + PReLU. 4 output channels x ROWS rows per thread.
// Block (32,8); tile = 32 cols x 8*ROWS rows. Grid (Wout/32, Hout/(8*ROWS),
// NB*Cout/4).
// in  : pointer at LOGICAL (0,0) of input  (pitch inPitch, plane inPlane)
// out : pointer at LOGICAL (0,0) of output (pitch outPitch, plane outPlane)
// PRED: bounds-check input loads (only needed for the unpadded img input).
// ---------------------------------------------------------------------------
template <int STRIDE, int ROWS, bool PRED>
__global__ void conv3x3_prelu(const float* __restrict__ in,
                              const float* __restrict__ wt,
                              const float* __restrict__ bias,
                              const float* __restrict__ alpha,
                              float* __restrict__ out,
                              int Cin, int Cout, int Hin, int Win,
                              int inPitch, size_t inPlane,
                              int outPitch, size_t outPlane) {
    const int Wout = Win / STRIDE;
    const int cg = Cout >> 2;
    const int co0 = (blockIdx.z % cg) * 4;
    const int n   = blockIdx.z / cg;

    extern __shared__ float sw[];            // [4][Cin][9]
    const int tid = threadIdx.y * 32 + threadIdx.x;
    const int nw = 4 * Cin * 9;
    const float* wsrc = wt + (size_t)co0 * Cin * 9;
    for (int i = tid; i < nw; i += 256) sw[i] = wsrc[i];
    __syncthreads();

    const int x  = blockIdx.x * 32 + threadIdx.x;
    const int y0 = blockIdx.y * (8 * ROWS) + threadIdx.y * ROWS;

    float acc[4][ROWS];
#pragma unroll
    for (int c = 0; c < 4; c++)
#pragma unroll
        for (int j = 0; j < ROWS; j++) acc[c][j] = 0.f;

    const float* ib = in + (size_t)n * Cin * inPlane;
    constexpr int NR = (STRIDE == 1) ? (ROWS + 2) : (2 * ROWS + 1);

    for (int ci = 0; ci < Cin; ci++) {
        const float* ip = ib + (size_t)ci * inPlane;
        float v[NR][3];
#pragma unroll
        for (int r = 0; r < NR; r++) {
            const int iy = STRIDE * y0 - 1 + r;
            const float* rp = ip + (ptrdiff_t)iy * inPitch + (STRIDE * x - 1);
            if (PRED) {
                bool yok = ((unsigned)iy < (unsigned)Hin);
#pragma unroll
                for (int c = 0; c < 3; c++) {
                    int ix = STRIDE * x - 1 + c;
                    v[r][c] = (yok && (unsigned)ix < (unsigned)Win) ? rp[c] : 0.f;
                }
            } else {
#pragma unroll
                for (int c = 0; c < 3; c++) v[r][c] = rp[c];
            }
        }
#pragma unroll
        for (int c4 = 0; c4 < 4; c4++) {
            const float* w9 = sw + (c4 * Cin + ci) * 9;
            float w[9];
#pragma unroll
            for (int k = 0; k < 9; k++) w[k] = w9[k];
#pragma unroll
            for (int j = 0; j < ROWS; j++)
#pragma unroll
                for (int ky = 0; ky < 3; ky++)
#pragma unroll
                    for (int kx = 0; kx < 3; kx++)
                        acc[c4][j] = fmaf(v[STRIDE * j + ky][kx], w[ky * 3 + kx], acc[c4][j]);
        }
    }

#pragma unroll
    for (int c4 = 0; c4 < 4; c4++) {
        const int co = co0 + c4;
        const float bv = bias[co];
        const float av = alpha[co];
        float* ob = out + (size_t)(n * Cout + co) * outPlane;
#pragma unroll
        for (int j = 0; j < ROWS; j++) {
            float o = acc[c4][j] + bv;
            o = (o >= 0.f) ? o : av * o;
            ob[(size_t)(y0 + j) * outPitch + x] = o;
        }
    }
    (void)Wout;
}

// ---------------------------------------------------------------------------
// Flow halving: 2x2 mean * 0.5 == sum * 0.125
// ---------------------------------------------------------------------------
__global__ void halve_flow_kernel(const float* __restrict__ in,
                                  float* __restrict__ out, int Hout, int Wout) {
    int idx = blockIdx.x * blockDim.x + threadIdx.x;
    int total = NB * 2 * Hout * Wout;
    if (idx >= total) return;
    int w = idx % Wout;
    int h = (idx / Wout) % Hout;
    int nc = idx / (Wout * Hout);
    int Win = 2 * Wout;
    const float* ip = in + (size_t)nc * (4 * Hout * Wout);
    const float* r0 = ip + (2 * h) * Win + 2 * w;
    const float* r1 = r0 + Win;
    out[idx] = (r0[0] + r0[1] + r1[0] + r1[1]) * 0.125f;
}

// ---------------------------------------------------------------------------
// Forward bilinear splat. feat is a PADDED region (pitch W+2).
// ---------------------------------------------------------------------------
__global__ void splat_add_kernel(const float* __restrict__ feat,
                                 const float* __restrict__ flow,
                                 float* __restrict__ num,
                                 float* __restrict__ cnt,
                                 int C, int H, int W) {
    int idx = blockIdx.x * blockDim.x + threadIdx.x;
    int HW = H * W;
    int total = NB * HW;
    if (idx >= total) return;
    int n = idx / HW;
    int p = idx % HW;
    int y = p / W;
    int x = p % W;

    const float* fb = flow + (size_t)n * 2 * HW;
    float fx = fb[p] + (float)x;
    float fy = fb[HW + p] + (float)y;

    float x0f = floorf(fx), y0f = floorf(fy);
    int ix0 = (int)x0f, iy0 = (int)y0f;
    float wx1 = fx - x0f, wy1 = fy - y0f;
    float wx0 = 1.f - wx1, wy0 = 1.f - wy1;

    int   xi[4] = {ix0, ix0 + 1, ix0,     ix0 + 1};
    int   yi[4] = {iy0, iy0,     iy0 + 1, iy0 + 1};
    float wv[4] = {wx0 * wy0, wx1 * wy0, wx0 * wy1, wx1 * wy1};
    int   tgt[4];
    bool  ok[4];
#pragma unroll
    for (int k = 0; k < 4; k++) {
        ok[k] = ((unsigned)xi[k] < (unsigned)W) && ((unsigned)yi[k] < (unsigned)H);
        tgt[k] = yi[k] * W + xi[k];
        if (ok[k]) atomicAdd(&cnt[n * HW + tgt[k]], wv[k]);
    }

    const size_t plane = (size_t)(H + 2) * (W + 2);
    const float* src = feat + (size_t)n * C * plane + (size_t)(y + 1) * (W + 2) + (x + 1);
    float* dst = num + (size_t)n * C * HW;
    for (int c = 0; c < C; c++) {
        float s = src[(size_t)c * plane];
        float* dc = dst + (size_t)c * HW;
#pragma unroll
        for (int k = 0; k < 4; k++)
            if (ok[k]) atomicAdd(&dc[tgt[k]], s * wv[k]);
    }
}

// ---------------------------------------------------------------------------
// num /= (cnt == 0 ? 1 : cnt)
// ---------------------------------------------------------------------------
__global__ void norm_div_kernel(float* __restrict__ num,
                                const float* __restrict__ cnt,
                                int C, int HW) {
    int idx = blockIdx.x * blockDim.x + threadIdx.x;
    int total = NB * C * HW;
    if (idx >= total) return;
    int n = idx / (C * HW);
    int p = idx % HW;
    float cv = cnt[n * HW + p];
    num[idx] = num[idx] / ((cv == 0.f) ? 1.f : cv);
}

// ---------------------------------------------------------------------------
// Host launcher
// ---------------------------------------------------------------------------
extern "C" void kernel_launch(void* const* d_in, const int* in_sizes, int n_in,
                              void* d_out, int out_size) {
    const float* img  = (const float*)d_in[0];
    const float* flow = (const float*)d_in[1];
    float* out = (float*)d_out;

    float *fa, *fb, *flA, *flB, *cnt;
    cudaGetSymbolAddress((void**)&fa,  g_fa);
    cudaGetSymbolAddress((void**)&fb,  g_fb);
    cudaGetSymbolAddress((void**)&flA, g_flA);
    cudaGetSymbolAddress((void**)&flB, g_flB);
    cudaGetSymbolAddress((void**)&cnt, g_cnt);
    float* flow_bufs[2] = {flA, flB};

    cudaMemsetAsync(d_out, 0, (size_t)out_size * sizeof(float));

    const int Cin[4]  = {3, 16, 32, 64};
    const int Cout[4] = {16, 32, 64, 128};
    const int Hin[4]  = {512, 256, 128, 64};

    // Per-level padded region offsets within fa/fb.
    size_t regOff[4];
    {
        size_t a = 0;
        for (int L = 0; L < 4; L++) {
            regOff[L] = a;
            int ho = Hin[L] / 2;
            a += (size_t)NB * Cout[L] * (ho + 2) * (ho + 2);
        }
    }

    // Zero all halo borders (both buffers, all levels).
    for (int L = 0; L < 4; L++) {
        int ho = Hin[L] / 2, co = Cout[L];
        int nc = NB * co;
        int per = 2 * (ho + 2) + 2 * ho;
        int tot = nc * per;
        zero_border_kernel<<<(tot + 255) / 256, 256>>>(fa + regOff[L], nc, ho, ho);
        zero_border_kernel<<<(tot + 255) / 256, 256>>>(fb + regOff[L], nc, ho, ho);
    }

    size_t off = 0;
    const float* flow_in = flow;

    for (int L = 0; L < 4; L++) {
        const int ci = Cin[L], co = Cout[L], hi = Hin[L], ho = hi / 2;
        const float* wA = (const float*)d_in[2 + 6 * L + 0];
        const float* bA = (const float*)d_in[2 + 6 * L + 1];
        const float* aA = (const float*)d_in[2 + 6 * L + 2];
        const float* wB = (const float*)d_in[2 + 6 * L + 3];
        const float* bB = (const float*)d_in[2 + 6 * L + 4];
        const float* aB = (const float*)d_in[2 + 6 * L + 5];

        const int po = ho + 2;                       // padded pitch at this level
        const size_t planeO = (size_t)po * po;       // padded plane
        float* faL = fa + regOff[L] + po + 1;        // logical (0,0)
        float* fbL = fb + regOff[L] + po + 1;

        // --- conv_a: stride 2, hi -> ho, ROWS=4 ---
        {
            dim3 blk(32, 8);
            dim3 grd(ho / 32, ho / 32, NB * (co / 4));
            size_t sm = 4 * ci * 9 * sizeof(float);
            if (L == 0) {
                // unpadded img input, predicated loads
                conv3x3_prelu<2, 4, true><<<grd, blk, sm>>>(
                    img, wA, bA, aA, faL, ci, co, hi, hi,
                    hi, (size_t)hi * hi, po, planeO);
            } else {
                // padded fb input from previous level
                const int pi = hi + 2;
                const float* inL = fb + regOff[L - 1] + pi + 1;
                conv3x3_prelu<2, 4, false><<<grd, blk, sm>>>(
                    inL, wA, bA, aA, faL, ci, co, hi, hi,
                    pi, (size_t)pi * pi, po, planeO);
            }
        }

        // --- conv_b: stride 1 at ho, ROWS=8 (or 4 for ho=32) ---
        {
            dim3 blk(32, 8);
            size_t sm = 4 * co * 9 * sizeof(float);
            if (ho >= 64) {
                dim3 grd(ho / 32, ho / 64, NB * (co / 4));
                conv3x3_prelu<1, 8, false><<<grd, blk, sm>>>(
                    faL, wB, bB, aB, fbL, co, co, ho, ho,
                    po, planeO, po, planeO);
            } else {
                dim3 grd(ho / 32, ho / 32, NB * (co / 4));
                conv3x3_prelu<1, 4, false><<<grd, blk, sm>>>(
                    faL, wB, bB, aB, fbL, co, co, ho, ho,
                    po, planeO, po, planeO);
            }
        }

        // --- halve flow: hi -> ho ---
        float* fl = flow_bufs[L & 1];
        {
            int nfl = NB * 2 * ho * ho;
            halve_flow_kernel<<<(nfl + 255) / 256, 256>>>(flow_in, fl, ho, ho);
        }

        // --- splat into output region ---
        cudaMemsetAsync(cnt, 0, (size_t)NB * ho * ho * sizeof(float));
        float* numL = out + off;
        {
            int np = NB * ho * ho;
            splat_add_kernel<<<(np + 255) / 256, 256>>>(
                fb + regOff[L], fl, numL, cnt, co, ho, ho);
        }
        {
            int ne = NB * co * ho * ho;
            norm_div_kernel<<<(ne + 255) / 256, 256>>>(numL, cnt, co, ho * ho);
        }

        off += (size_t)NB * co * ho * ho;
        flow_in = fl;
    }
}